// round 15
// baseline (speedup 1.0000x reference)
#include <cuda_runtime.h>
#include <cuda_fp16.h>
#include <cstdint>
#include <math.h>

#define NN     256
#define NCOIL  8
#define KTOT   17408
#define NVEC   512
#define KT_CTA 64
#define NCTA   (KTOT / KT_CTA)     // 272

#define TBLB   65536               // E2 table: 4kw x 8bq x 2blk x 2pl x 512B
#define SMEM_BYTES TBLB
#define SLABH  2048                // halves per (coil,ach,bq) slab (4KB)
#define SLABB  4096                // bytes per slab
#define COILSTRIDE (64 * SLABB)    // bytes per coil in gXh (262144)

// packed fp16 Xc blobs (R/I chunks), chunk idx = col*8 + blk*4 + q
// chunk content (16B): [Xr(hi0p0),Xr(hi0p1),Xr(hi1p0),Xr(hi1p1), Xi x4]
__device__ __half gXh[(size_t)NCOIL * 64 * SLABH];

// ------------------------- helpers -------------------------
__device__ __forceinline__ uint32_t smem_u32(const void* p) {
    uint32_t a;
    asm("{ .reg .u64 t; cvta.to.shared.u64 t, %1; cvt.u32.u64 %0, t; }"
        : "=r"(a) : "l"(p));
    return a;
}
__device__ __forceinline__ uint32_t pack2(float lo, float hi) {
    __half2 h = __floats2half2_rn(lo, hi);
    return *reinterpret_cast<uint32_t*>(&h);
}
__device__ __forceinline__ uint32_t hadd2u(uint32_t a, uint32_t b) {
    uint32_t d;
    asm("add.f16x2 %0, %1, %2;" : "=r"(d) : "r"(a), "r"(b));
    return d;
}
__device__ __forceinline__ void lds128(uint32_t& a, uint32_t& b, uint32_t& c,
                                       uint32_t& d, uint32_t addr) {
    asm("ld.shared.v4.b32 {%0,%1,%2,%3}, [%4];"
        : "=r"(a), "=r"(b), "=r"(c), "=r"(d) : "r"(addr));
}
__device__ __forceinline__ void sts128(uint32_t addr, const uint32_t* v) {
    asm volatile("st.shared.v4.b32 [%0], {%1,%2,%3,%4};"
                 :: "r"(addr), "r"(v[0]), "r"(v[1]), "r"(v[2]), "r"(v[3]));
}
// fp16 m16n8k16 mma, fp32 accumulate
__device__ __forceinline__ void mma16(float* d, const uint32_t* A,
                                      uint32_t b0, uint32_t b1) {
    asm volatile(
        "mma.sync.aligned.m16n8k16.row.col.f32.f16.f16.f32 "
        "{%0,%1,%2,%3}, {%4,%5,%6,%7}, {%8,%9}, {%0,%1,%2,%3};"
        : "+f"(d[0]), "+f"(d[1]), "+f"(d[2]), "+f"(d[3])
        : "r"(A[0]), "r"(A[1]), "r"(A[2]), "r"(A[3]), "r"(b0), "r"(b1));
}

// ------------------------- prep -------------------------
__global__ void prep_X(const float* __restrict__ input_r,
                       const float* __restrict__ C_r) {
    int idx = blockIdx.x * blockDim.x + threadIdx.x;   // (c*256+a)*256 + b
    if (idx >= NCOIL * NN * NN) return;
    int c = idx >> 16;
    int a = (idx >> 8) & 255;
    int b = idx & 255;
    float xr = input_r[(a * NN + b) * 2 + 0];
    float xi = input_r[(a * NN + b) * 2 + 1];
    float cr = C_r[(size_t)idx * 2 + 0];
    float ci = C_r[(size_t)idx * 2 + 1];
    float Xr = cr * xr - ci * xi;
    float Xi = cr * xi + ci * xr;

    int ach = a >> 5, col = a & 31;
    int bq = b >> 5, bl = b & 31;
    int blk = bl >> 4, kk = bl & 15;
    int hi = kk >> 3, q = (kk & 7) >> 1, part = kk & 1;

    size_t base = ((size_t)c * 64 + ach * 8 + bq) * SLABH;
    int chA = col * 8 + blk * 4 + q;
    gXh[base + chA * 8 + 0 + hi * 2 + part] = __float2half_rn(Xr);
    gXh[base + chA * 8 + 4 + hi * 2 + part] = __float2half_rn(Xi);
}

// ------------------------- main -------------------------
extern __shared__ char dyn_smem[];

__global__ void __launch_bounds__(256, 2)
main_kernel(const float* __restrict__ angle, const float* __restrict__ w,
            float* __restrict__ out) {
    __shared__ float2 sred[2][KT_CTA];

    const uint32_t TBL = smem_u32(dyn_smem);
    const int tid  = threadIdx.x;
    const int lane = tid & 31;
    const int warp = tid >> 5;
    const int kw   = warp & 3;        // k-subtile (16 rows)
    const int nw   = warp >> 2;       // a-half (16 cols)
    const int r    = lane >> 2;
    const int q    = lane & 3;
    const int kblk = blockIdx.x * KT_CTA;

    const int k0g = kblk + kw * 16 + r;
    const int k1g = k0g + 8;
    const float t0 = angle[2 * k0g + 1];
    const float t1 = angle[2 * k1g + 1];

    // E1 epilogue constants (compact persistent set)
    const float s_[2] = {angle[2 * k0g], angle[2 * k1g]};
    float advr[2], advi[2], fc0r[2], fc0i[2], f1r[2], f1i[2];
    {
        const int co0 = nw * 16 + 2 * q;
#pragma unroll
        for (int m = 0; m < 2; ++m) {
            sincosf(32.0f * s_[m], &advi[m], &advr[m]);
            sincosf(s_[m] * (float)co0, &fc0i[m], &fc0r[m]);
            sincosf(s_[m], &f1i[m], &f1r[m]);
        }
    }

    // ---- generate E2 fragment table (once per CTA; nw==0 warps) ----
    if (nw == 0) {
        float er_[2][2], ei_[2][2];
        sincosf(t0 * (float)(2 * q - 128), &ei_[0][0], &er_[0][0]);
        sincosf(t0 * (float)(2 * q - 120), &ei_[0][1], &er_[0][1]);
        sincosf(t1 * (float)(2 * q - 128), &ei_[1][0], &er_[1][0]);
        sincosf(t1 * (float)(2 * q - 120), &ei_[1][1], &er_[1][1]);
        float r1r[2], r1i[2], st16r[2], st16i[2];
        sincosf(t0, &r1i[0], &r1r[0]);
        sincosf(t1, &r1i[1], &r1r[1]);
        sincosf(16.0f * t0, &st16i[0], &st16r[0]);
        sincosf(16.0f * t1, &st16i[1], &st16r[1]);

        uint32_t ga = TBL + (uint32_t)kw * 16384 + (uint32_t)lane * 16;
#pragma unroll 4
        for (int bb2 = 0; bb2 < 16; ++bb2) {
            uint32_t Ar[4], Ai[4];
#pragma unroll
            for (int o = 0; o < 2; ++o)
#pragma unroll
                for (int m = 0; m < 2; ++m) {
                    float br = er_[m][o], bi = ei_[m][o];
                    float nr2 = br * r1r[m] - bi * r1i[m];
                    float ni2 = br * r1i[m] + bi * r1r[m];
                    int idx = o * 2 + m;
                    Ar[idx] = pack2(br, nr2);
                    Ai[idx] = pack2(bi, ni2);
                }
            sts128(ga, Ar);
            sts128(ga + 512, Ai);
            ga += 1024;
#pragma unroll
            for (int m = 0; m < 2; ++m)
#pragma unroll
                for (int o = 0; o < 2; ++o) {
                    float nr2 = er_[m][o] * st16r[m] - ei_[m][o] * st16i[m];
                    ei_[m][o] = fmaf(er_[m][o], st16i[m], ei_[m][o] * st16r[m]);
                    er_[m][o] = nr2;
                }
        }
    }
    __syncthreads();   // table ready; last CTA-wide barrier before writeouts

    float yr[2][2] = {}, yi[2][2] = {};
    float runr[2], runi[2];
#pragma unroll
    for (int m = 0; m < 2; ++m) sincosf(-128.0f * s_[m], &runi[m], &runr[m]);

    const uint32_t TA0 = TBL + (uint32_t)kw * 16384 + (uint32_t)lane * 16;
    // per-thread global fragment offset: col = nw*16 + nt*8 + r, chunk q
    const uint32_t goff = (uint32_t)((nw * 16 + r) * 128 + q * 16);

#pragma unroll 1
    for (int cp = 0; cp < 4; ++cp) {
#pragma unroll 1
        for (int ach = 0; ach < 8; ++ach) {
            float P1[2][2][4] = {}, P2[2][2][4] = {}, P3[2][2][4] = {};
            const char* abase = (const char*)gXh
                + (size_t)(cp * 128 + ach * 8) * SLABB + goff;

#pragma unroll 2
            for (int bq = 0; bq < 8; ++bq) {
                const char* sb = abase + (size_t)bq * SLABB;
                const uint32_t TA = TA0 + (uint32_t)bq * 2048;
#pragma unroll
                for (int blk = 0; blk < 2; ++blk) {
                    // batch the 4 independent B fragment loads (MLP=4)
                    uint4 B[2][2];
#pragma unroll
                    for (int ci = 0; ci < 2; ++ci)
#pragma unroll
                        for (int nt = 0; nt < 2; ++nt)
                            B[ci][nt] = __ldg((const uint4*)(sb
                                + ci * COILSTRIDE + nt * 1024 + blk * 64));

                    uint32_t Ar[4], Ai[4], As[4];
                    lds128(Ar[0], Ar[1], Ar[2], Ar[3], TA + blk * 1024);
                    lds128(Ai[0], Ai[1], Ai[2], Ai[3], TA + blk * 1024 + 512);
#pragma unroll
                    for (int j = 0; j < 4; ++j) As[j] = hadd2u(Ar[j], Ai[j]);
#pragma unroll
                    for (int ci = 0; ci < 2; ++ci)
#pragma unroll
                        for (int nt = 0; nt < 2; ++nt) {
                            uint32_t rlo = B[ci][nt].x, rhi = B[ci][nt].y;
                            uint32_t ilo = B[ci][nt].z, ihi = B[ci][nt].w;
                            uint32_t slo = hadd2u(rlo, ilo);
                            uint32_t shi = hadd2u(rhi, ihi);
                            mma16(P1[ci][nt], Ar, rlo, rhi);
                            mma16(P2[ci][nt], Ai, ilo, ihi);
                            mma16(P3[ci][nt], As, slo, shi);
                        }
                }
            }

            // ---- epilogue: y += e1 * T (3M combine) ----
#pragma unroll
            for (int m = 0; m < 2; ++m) {
                // f8 = f1^8 by repeated squaring
                float c2 = f1r[m] * f1r[m] - f1i[m] * f1i[m];
                float sq2 = 2.0f * f1r[m] * f1i[m];
                float c4 = c2 * c2 - sq2 * sq2;
                float sq4 = 2.0f * c2 * sq2;
                float f8r = c4 * c4 - sq4 * sq4;
                float f8i = 2.0f * c4 * sq4;

                float b0r = runr[m] * fc0r[m] - runi[m] * fc0i[m];
                float b0i = runr[m] * fc0i[m] + runi[m] * fc0r[m];
#pragma unroll
                for (int nt = 0; nt < 2; ++nt) {
                    float cr_ = b0r, ci_ = b0i;
                    if (nt == 1) {
                        cr_ = b0r * f8r - b0i * f8i;
                        ci_ = b0r * f8i + b0i * f8r;
                    }
#pragma unroll
                    for (int j = 0; j < 2; ++j) {
                        float er2 = cr_, ei2 = ci_;
                        if (j == 1) {
                            er2 = cr_ * f1r[m] - ci_ * f1i[m];
                            ei2 = cr_ * f1i[m] + ci_ * f1r[m];
                        }
                        int e = m * 2 + j;
#pragma unroll
                        for (int ci2 = 0; ci2 < 2; ++ci2) {
                            float p1 = P1[ci2][nt][e], p2 = P2[ci2][nt][e];
                            float Tr = p1 - p2;
                            float Ti = P3[ci2][nt][e] - p1 - p2;
                            yr[ci2][m] = fmaf(er2, Tr, yr[ci2][m]);
                            yr[ci2][m] = fmaf(-ei2, Ti, yr[ci2][m]);
                            yi[ci2][m] = fmaf(er2, Ti, yi[ci2][m]);
                            yi[ci2][m] = fmaf(ei2, Tr, yi[ci2][m]);
                        }
                    }
                }
                // advance run by exp(i*32*s)
                float nr2 = runr[m] * advr[m] - runi[m] * advi[m];
                runi[m] = fmaf(runr[m], advi[m], runi[m] * advr[m]);
                runr[m] = nr2;
            }
        } // ach

        // ---- writeout coil pair cp ----
#pragma unroll
        for (int ci = 0; ci < 2; ++ci)
#pragma unroll
            for (int m = 0; m < 2; ++m) {
                yr[ci][m] += __shfl_xor_sync(0xffffffffu, yr[ci][m], 1);
                yr[ci][m] += __shfl_xor_sync(0xffffffffu, yr[ci][m], 2);
                yi[ci][m] += __shfl_xor_sync(0xffffffffu, yi[ci][m], 1);
                yi[ci][m] += __shfl_xor_sync(0xffffffffu, yi[ci][m], 2);
            }
        __syncthreads();   // sred slot reuse safety across cp iterations
        if (nw == 1 && q == 0) {
            sred[0][kw * 16 + r]     = make_float2(yr[0][0], yi[0][0]);
            sred[0][kw * 16 + 8 + r] = make_float2(yr[0][1], yi[0][1]);
            sred[1][kw * 16 + r]     = make_float2(yr[1][0], yi[1][0]);
            sred[1][kw * 16 + 8 + r] = make_float2(yr[1][1], yi[1][1]);
        }
        __syncthreads();
        if (nw == 0 && q == 0) {
            const float wk0 = w[k0g & (NVEC - 1)];
            const float wk1 = w[k1g & (NVEC - 1)];
            int c0 = cp * 2;
#pragma unroll
            for (int ci = 0; ci < 2; ++ci) {
                float2 p0 = sred[ci][kw * 16 + r];
                float2 p1 = sred[ci][kw * 16 + 8 + r];
                size_t o0 = ((size_t)(c0 + ci) * KTOT + k0g) * 2;
                size_t o1 = ((size_t)(c0 + ci) * KTOT + k1g) * 2;
                out[o0 + 0] = (yr[ci][0] + p0.x) * wk0;
                out[o0 + 1] = (yi[ci][0] + p0.y) * wk0;
                out[o1 + 0] = (yr[ci][1] + p1.x) * wk1;
                out[o1 + 1] = (yi[ci][1] + p1.y) * wk1;
            }
        }
#pragma unroll
        for (int ci = 0; ci < 2; ++ci)
#pragma unroll
            for (int m = 0; m < 2; ++m) { yr[ci][m] = 0.f; yi[ci][m] = 0.f; }
#pragma unroll
        for (int m = 0; m < 2; ++m)
            sincosf(-128.0f * s_[m], &runi[m], &runr[m]);
    } // cp
}

// ------------------------- launch -------------------------
extern "C" void kernel_launch(void* const* d_in, const int* in_sizes, int n_in,
                              void* d_out, int out_size) {
    const float* input_r = (const float*)d_in[0];
    const float* C_r     = (const float*)d_in[1];
    const float* w       = (const float*)d_in[2];
    const float* angle   = (const float*)d_in[3];
    float* out = (float*)d_out;

    prep_X<<<(NCOIL * NN * NN + 255) / 256, 256>>>(input_r, C_r);

    cudaFuncSetAttribute(main_kernel,
                         cudaFuncAttributeMaxDynamicSharedMemorySize, SMEM_BYTES);
    main_kernel<<<NCTA, 256, SMEM_BYTES>>>(angle, w, out);
}

// round 16
// speedup vs baseline: 1.1649x; 1.1649x over previous
#include <cuda_runtime.h>
#include <cuda_fp16.h>
#include <cstdint>
#include <math.h>

#define NN     256
#define NCOIL  8
#define KTOT   17408
#define NVEC   512
#define KT_CTA 128
#define NCTA   (KTOT / KT_CTA)     // 136
#define THREADS 512

// stage: 2 coils x 32 a-cols x 32 b, fp16, parity-swizzled
#define COILB  4096                // 32 cols x 128B
#define STAGEB (2 * COILB)         // 8192
#define NBUF   8
#define RINGB  (NBUF * STAGEB)     // 65536
#define TBLB   131072              // E2 table: 8kw x 8bq x 2blk x 2pl x 512B
#define SMEM_BYTES (RINGB + TBLB)  // 196608
#define NSTAGE 256                 // 4 coil-pairs x 8 ach x 8 bq
#define SLABH  2048                // halves per (coil,ach,bq) slab (4KB)

// packed fp16 Xc blobs (R/I chunks), chunk idx = col*8 + blk*4 + q
__device__ __half gXh[(size_t)NCOIL * 64 * SLABH];

// ------------------------- helpers -------------------------
__device__ __forceinline__ uint32_t smem_u32(const void* p) {
    uint32_t a;
    asm("{ .reg .u64 t; cvta.to.shared.u64 t, %1; cvt.u32.u64 %0, t; }"
        : "=r"(a) : "l"(p));
    return a;
}
__device__ __forceinline__ uint32_t pack2(float lo, float hi) {
    __half2 h = __floats2half2_rn(lo, hi);
    return *reinterpret_cast<uint32_t*>(&h);
}
__device__ __forceinline__ uint32_t hadd2u(uint32_t a, uint32_t b) {
    uint32_t d;
    asm("add.f16x2 %0, %1, %2;" : "=r"(d) : "r"(a), "r"(b));
    return d;
}
__device__ __forceinline__ void cp16(uint32_t dst, const void* src) {
    asm volatile("cp.async.cg.shared.global [%0], [%1], 16;"
                 :: "r"(dst), "l"(src) : "memory");
}
#define CP_COMMIT() asm volatile("cp.async.commit_group;" ::: "memory")
#define CP_WAIT0()  asm volatile("cp.async.wait_group 0;" ::: "memory")

__device__ __forceinline__ void lds128(uint32_t& a, uint32_t& b, uint32_t& c,
                                       uint32_t& d, uint32_t addr) {
    asm("ld.shared.v4.b32 {%0,%1,%2,%3}, [%4];"
        : "=r"(a), "=r"(b), "=r"(c), "=r"(d) : "r"(addr));
}
__device__ __forceinline__ void sts128(uint32_t addr, const uint32_t* v) {
    asm volatile("st.shared.v4.b32 [%0], {%1,%2,%3,%4};"
                 :: "r"(addr), "r"(v[0]), "r"(v[1]), "r"(v[2]), "r"(v[3]));
}
// fp16 m16n8k16 mma, fp32 accumulate
__device__ __forceinline__ void mma16(float* d, const uint32_t* A,
                                      uint32_t b0, uint32_t b1) {
    asm volatile(
        "mma.sync.aligned.m16n8k16.row.col.f32.f16.f16.f32 "
        "{%0,%1,%2,%3}, {%4,%5,%6,%7}, {%8,%9}, {%0,%1,%2,%3};"
        : "+f"(d[0]), "+f"(d[1]), "+f"(d[2]), "+f"(d[3])
        : "r"(A[0]), "r"(A[1]), "r"(A[2]), "r"(A[3]), "r"(b0), "r"(b1));
}

// ------------------------- prep -------------------------
__global__ void prep_X(const float* __restrict__ input_r,
                       const float* __restrict__ C_r) {
    int idx = blockIdx.x * blockDim.x + threadIdx.x;   // (c*256+a)*256 + b
    if (idx >= NCOIL * NN * NN) return;
    int c = idx >> 16;
    int a = (idx >> 8) & 255;
    int b = idx & 255;
    float xr = input_r[(a * NN + b) * 2 + 0];
    float xi = input_r[(a * NN + b) * 2 + 1];
    float cr = C_r[(size_t)idx * 2 + 0];
    float ci = C_r[(size_t)idx * 2 + 1];
    float Xr = cr * xr - ci * xi;
    float Xi = cr * xi + ci * xr;

    int ach = a >> 5, col = a & 31;
    int bq = b >> 5, bl = b & 31;
    int blk = bl >> 4, kk = bl & 15;
    int hi = kk >> 3, q = (kk & 7) >> 1, part = kk & 1;

    size_t base = ((size_t)c * 64 + ach * 8 + bq) * SLABH;
    int chA = col * 8 + blk * 4 + q;
    gXh[base + chA * 8 + 0 + hi * 2 + part] = __float2half_rn(Xr);
    gXh[base + chA * 8 + 4 + hi * 2 + part] = __float2half_rn(Xi);
}

// ------------------------- main -------------------------
extern __shared__ char dyn_smem[];

__global__ void __launch_bounds__(THREADS, 1)
main_kernel(const float* __restrict__ angle, const float* __restrict__ w,
            float* __restrict__ out) {
    __shared__ float2 sred[2][KT_CTA];

    const uint32_t XST = smem_u32(dyn_smem);
    const uint32_t TBL = XST + RINGB;
    const int tid  = threadIdx.x;
    const int lane = tid & 31;
    const int warp = tid >> 5;
    const int kw   = warp & 7;        // k-subtile (16 rows, 8 of them = 128 k)
    const int nw   = warp >> 3;       // a-half (16 cols)
    const int r    = lane >> 2;
    const int q    = lane & 3;
    const int kblk = blockIdx.x * KT_CTA;

    const int k0g = kblk + kw * 16 + r;
    const int k1g = k0g + 8;
    const float t0 = angle[2 * k0g + 1];
    const float t1 = angle[2 * k1g + 1];

    // E1 epilogue constants (compact persistent set)
    const float s_[2] = {angle[2 * k0g], angle[2 * k1g]};
    float advr[2], advi[2], fc0r[2], fc0i[2], f1r[2], f1i[2];
    {
        const int co0 = nw * 16 + 2 * q;
#pragma unroll
        for (int m = 0; m < 2; ++m) {
            sincosf(32.0f * s_[m], &advi[m], &advr[m]);
            sincosf(s_[m] * (float)co0, &fc0i[m], &fc0r[m]);
            sincosf(s_[m], &f1i[m], &f1r[m]);
        }
    }

    // loader: one STAGE = 512 16B-chunks, 1 per thread; parity swizzle
    auto issue_stage = [&](int st) {
        int cp_ = st >> 6, ach = (st >> 3) & 7, bq = st & 7;
        const char* src =
            (const char*)(gXh + (size_t)((cp_ * 16 + ach) * 8 + bq) * SLABH);
        uint32_t dst = XST + (uint32_t)(st & 7) * STAGEB;
        int ci  = tid >> 8;
        int loc = tid & 255;
        int col = loc >> 3, blk = (loc >> 2) & 1, qq = loc & 3;
        uint32_t doff = (uint32_t)(ci * COILB + col * 128 +
                        ((blk * 64 + qq * 16) ^ ((col & 1) * 64)));
        cp16(dst + doff, src + (size_t)ci * (64 * SLABH * 2) + loc * 16);
    };

    // prologue: window 0 (4 stages) in flight
    issue_stage(0); issue_stage(1); issue_stage(2); issue_stage(3);
    CP_COMMIT();

    // ---- generate E2 fragment table (once per CTA; nw==0 warps, 8 kw) ----
    if (nw == 0) {
        float er_[2][2], ei_[2][2];
        sincosf(t0 * (float)(2 * q - 128), &ei_[0][0], &er_[0][0]);
        sincosf(t0 * (float)(2 * q - 120), &ei_[0][1], &er_[0][1]);
        sincosf(t1 * (float)(2 * q - 128), &ei_[1][0], &er_[1][0]);
        sincosf(t1 * (float)(2 * q - 120), &ei_[1][1], &er_[1][1]);
        float r1r[2], r1i[2], st16r[2], st16i[2];
        sincosf(t0, &r1i[0], &r1r[0]);
        sincosf(t1, &r1i[1], &r1r[1]);
        sincosf(16.0f * t0, &st16i[0], &st16r[0]);
        sincosf(16.0f * t1, &st16i[1], &st16r[1]);

        uint32_t ga = TBL + (uint32_t)kw * 16384 + (uint32_t)lane * 16;
#pragma unroll 4
        for (int bb2 = 0; bb2 < 16; ++bb2) {
            uint32_t Ar[4], Ai[4];
#pragma unroll
            for (int o = 0; o < 2; ++o)
#pragma unroll
                for (int m = 0; m < 2; ++m) {
                    float br = er_[m][o], bi = ei_[m][o];
                    float nr2 = br * r1r[m] - bi * r1i[m];
                    float ni2 = br * r1i[m] + bi * r1r[m];
                    int idx = o * 2 + m;
                    Ar[idx] = pack2(br, nr2);
                    Ai[idx] = pack2(bi, ni2);
                }
            sts128(ga, Ar);
            sts128(ga + 512, Ai);
            ga += 1024;
#pragma unroll
            for (int m = 0; m < 2; ++m)
#pragma unroll
                for (int o = 0; o < 2; ++o) {
                    float nr2 = er_[m][o] * st16r[m] - ei_[m][o] * st16i[m];
                    ei_[m][o] = fmaf(er_[m][o], st16i[m], ei_[m][o] * st16r[m]);
                    er_[m][o] = nr2;
                }
        }
    }

    float yr[2][2] = {}, yi[2][2] = {};
    float runr[2], runi[2];
#pragma unroll
    for (int m = 0; m < 2; ++m) sincosf(-128.0f * s_[m], &runi[m], &runr[m]);

    const uint32_t TA0 = TBL + (uint32_t)kw * 16384 + (uint32_t)lane * 16;
    const uint32_t swz  = (uint32_t)((r & 1) * 64);
    const uint32_t ob0  = (uint32_t)(q * 16) + swz;
    const uint32_t ob1  = (uint32_t)(q * 16) + (64u ^ swz);
    int st = 0;

#pragma unroll 1
    for (int cp = 0; cp < 4; ++cp) {
#pragma unroll 1
        for (int ach = 0; ach < 8; ++ach) {
            float P1[2][2][4] = {}, P2[2][2][4] = {}, P3[2][2][4] = {};

#pragma unroll 1
            for (int grp = 0; grp < 2; ++grp) {       // windows of 4 bq stages
                CP_WAIT0();
                __syncthreads();
                if (st + 4 < NSTAGE) {
                    issue_stage(st + 4); issue_stage(st + 5);
                    issue_stage(st + 6); issue_stage(st + 7);
                    CP_COMMIT();
                }
#pragma unroll
                for (int h = 0; h < 4; ++h) {
                    const int s = st + h;
                    const uint32_t bb  = XST + (uint32_t)(s & 7) * STAGEB;
                    const uint32_t riB = bb + (uint32_t)(nw * 16 + r) * 128;
                    const uint32_t TA  = TA0 + (uint32_t)(s & 7) * 2048;
#pragma unroll
                    for (int blk = 0; blk < 2; ++blk) {
                        uint32_t Ar[4], Ai[4], As[4];
                        lds128(Ar[0], Ar[1], Ar[2], Ar[3], TA + blk * 1024);
                        lds128(Ai[0], Ai[1], Ai[2], Ai[3], TA + blk * 1024 + 512);
#pragma unroll
                        for (int j = 0; j < 4; ++j) As[j] = hadd2u(Ar[j], Ai[j]);
                        const uint32_t ob = blk ? ob1 : ob0;
#pragma unroll
                        for (int ci = 0; ci < 2; ++ci)
#pragma unroll
                            for (int nt = 0; nt < 2; ++nt) {
                                uint32_t rlo, rhi, ilo, ihi;
                                lds128(rlo, rhi, ilo, ihi,
                                       riB + ci * COILB + nt * 1024 + ob);
                                uint32_t slo = hadd2u(rlo, ilo);
                                uint32_t shi = hadd2u(rhi, ihi);
                                mma16(P1[ci][nt], Ar, rlo, rhi);
                                mma16(P2[ci][nt], Ai, ilo, ihi);
                                mma16(P3[ci][nt], As, slo, shi);
                            }
                    }
                }
                st += 4;
            }

            // ---- epilogue: y += e1 * T (3M combine) ----
#pragma unroll
            for (int m = 0; m < 2; ++m) {
                // f8 = f1^8 by repeated squaring
                float c2 = f1r[m] * f1r[m] - f1i[m] * f1i[m];
                float sq2 = 2.0f * f1r[m] * f1i[m];
                float c4 = c2 * c2 - sq2 * sq2;
                float sq4 = 2.0f * c2 * sq2;
                float f8r = c4 * c4 - sq4 * sq4;
                float f8i = 2.0f * c4 * sq4;

                float b0r = runr[m] * fc0r[m] - runi[m] * fc0i[m];
                float b0i = runr[m] * fc0i[m] + runi[m] * fc0r[m];
#pragma unroll
                for (int nt = 0; nt < 2; ++nt) {
                    float cr_ = b0r, ci_ = b0i;
                    if (nt == 1) {
                        cr_ = b0r * f8r - b0i * f8i;
                        ci_ = b0r * f8i + b0i * f8r;
                    }
#pragma unroll
                    for (int j = 0; j < 2; ++j) {
                        float er2 = cr_, ei2 = ci_;
                        if (j == 1) {
                            er2 = cr_ * f1r[m] - ci_ * f1i[m];
                            ei2 = cr_ * f1i[m] + ci_ * f1r[m];
                        }
                        int e = m * 2 + j;
#pragma unroll
                        for (int ci2 = 0; ci2 < 2; ++ci2) {
                            float p1 = P1[ci2][nt][e], p2 = P2[ci2][nt][e];
                            float Tr = p1 - p2;
                            float Ti = P3[ci2][nt][e] - p1 - p2;
                            yr[ci2][m] = fmaf(er2, Tr, yr[ci2][m]);
                            yr[ci2][m] = fmaf(-ei2, Ti, yr[ci2][m]);
                            yi[ci2][m] = fmaf(er2, Ti, yi[ci2][m]);
                            yi[ci2][m] = fmaf(ei2, Tr, yi[ci2][m]);
                        }
                    }
                }
                // advance run by exp(i*32*s)
                float nr2 = runr[m] * advr[m] - runi[m] * advi[m];
                runi[m] = fmaf(runr[m], advi[m], runi[m] * advr[m]);
                runr[m] = nr2;
            }
        } // ach

        // ---- writeout coil pair cp ----
#pragma unroll
        for (int ci = 0; ci < 2; ++ci)
#pragma unroll
            for (int m = 0; m < 2; ++m) {
                yr[ci][m] += __shfl_xor_sync(0xffffffffu, yr[ci][m], 1);
                yr[ci][m] += __shfl_xor_sync(0xffffffffu, yr[ci][m], 2);
                yi[ci][m] += __shfl_xor_sync(0xffffffffu, yi[ci][m], 1);
                yi[ci][m] += __shfl_xor_sync(0xffffffffu, yi[ci][m], 2);
            }
        if (nw == 1 && q == 0) {
            sred[0][kw * 16 + r]     = make_float2(yr[0][0], yi[0][0]);
            sred[0][kw * 16 + 8 + r] = make_float2(yr[0][1], yi[0][1]);
            sred[1][kw * 16 + r]     = make_float2(yr[1][0], yi[1][0]);
            sred[1][kw * 16 + 8 + r] = make_float2(yr[1][1], yi[1][1]);
        }
        __syncthreads();
        if (nw == 0 && q == 0) {
            const float wk0 = w[k0g & (NVEC - 1)];
            const float wk1 = w[k1g & (NVEC - 1)];
            int c0 = cp * 2;
#pragma unroll
            for (int ci = 0; ci < 2; ++ci) {
                float2 p0 = sred[ci][kw * 16 + r];
                float2 p1 = sred[ci][kw * 16 + 8 + r];
                size_t o0 = ((size_t)(c0 + ci) * KTOT + k0g) * 2;
                size_t o1 = ((size_t)(c0 + ci) * KTOT + k1g) * 2;
                out[o0 + 0] = (yr[ci][0] + p0.x) * wk0;
                out[o0 + 1] = (yi[ci][0] + p0.y) * wk0;
                out[o1 + 0] = (yr[ci][1] + p1.x) * wk1;
                out[o1 + 1] = (yi[ci][1] + p1.y) * wk1;
            }
        }
        __syncthreads();   // sred reuse safety
#pragma unroll
        for (int ci = 0; ci < 2; ++ci)
#pragma unroll
            for (int m = 0; m < 2; ++m) { yr[ci][m] = 0.f; yi[ci][m] = 0.f; }
#pragma unroll
        for (int m = 0; m < 2; ++m)
            sincosf(-128.0f * s_[m], &runi[m], &runr[m]);
    } // cp
}

// ------------------------- launch -------------------------
extern "C" void kernel_launch(void* const* d_in, const int* in_sizes, int n_in,
                              void* d_out, int out_size) {
    const float* input_r = (const float*)d_in[0];
    const float* C_r     = (const float*)d_in[1];
    const float* w       = (const float*)d_in[2];
    const float* angle   = (const float*)d_in[3];
    float* out = (float*)d_out;

    prep_X<<<(NCOIL * NN * NN + 255) / 256, 256>>>(input_r, C_r);

    cudaFuncSetAttribute(main_kernel,
                         cudaFuncAttributeMaxDynamicSharedMemorySize, SMEM_BYTES);
    main_kernel<<<NCTA, THREADS, SMEM_BYTES>>>(angle, w, out);
}

// round 17
// speedup vs baseline: 1.1950x; 1.0259x over previous
#include <cuda_runtime.h>
#include <cuda_fp16.h>
#include <cstdint>
#include <math.h>

#define NN     256
#define NCOIL  8
#define KTOT   17408
#define NVEC   512
#define KT_CTA 128
#define NCTA   (KTOT / KT_CTA)     // 136
#define THREADS 512

// stage: 2 coils x 32 a-cols x 32 b, fp16, parity-swizzled
#define COILB  4096                // 32 cols x 128B
#define STAGEB (2 * COILB)         // 8192
#define NBUF   8
#define RINGB  (NBUF * STAGEB)     // 65536
#define TBLB   131072              // E2 table: 8kw x 8bq x 2blk x 2pl x 512B
#define EPIB   (THREADS * 48)      // 24576: per-thread epilogue constants
#define SMEM_BYTES (RINGB + TBLB + EPIB)   // 221184
#define NSTAGE 256                 // 4 coil-pairs x 8 ach x 8 bq
#define SLABH  2048                // halves per (coil,ach,bq) slab (4KB)

// packed fp16 Xc blobs (R/I chunks), chunk idx = col*8 + blk*4 + q
__device__ __half gXh[(size_t)NCOIL * 64 * SLABH];

// ------------------------- helpers -------------------------
__device__ __forceinline__ uint32_t smem_u32(const void* p) {
    uint32_t a;
    asm("{ .reg .u64 t; cvta.to.shared.u64 t, %1; cvt.u32.u64 %0, t; }"
        : "=r"(a) : "l"(p));
    return a;
}
__device__ __forceinline__ uint32_t pack2(float lo, float hi) {
    __half2 h = __floats2half2_rn(lo, hi);
    return *reinterpret_cast<uint32_t*>(&h);
}
__device__ __forceinline__ uint32_t hadd2u(uint32_t a, uint32_t b) {
    uint32_t d;
    asm("add.f16x2 %0, %1, %2;" : "=r"(d) : "r"(a), "r"(b));
    return d;
}
__device__ __forceinline__ void cp16(uint32_t dst, const void* src) {
    asm volatile("cp.async.cg.shared.global [%0], [%1], 16;"
                 :: "r"(dst), "l"(src) : "memory");
}
#define CP_COMMIT() asm volatile("cp.async.commit_group;" ::: "memory")
#define CP_WAIT0()  asm volatile("cp.async.wait_group 0;" ::: "memory")

__device__ __forceinline__ void lds128(uint32_t& a, uint32_t& b, uint32_t& c,
                                       uint32_t& d, uint32_t addr) {
    asm("ld.shared.v4.b32 {%0,%1,%2,%3}, [%4];"
        : "=r"(a), "=r"(b), "=r"(c), "=r"(d) : "r"(addr));
}
__device__ __forceinline__ void lds128f(float& a, float& b, float& c, float& d,
                                        uint32_t addr) {
    asm("ld.shared.v4.f32 {%0,%1,%2,%3}, [%4];"
        : "=f"(a), "=f"(b), "=f"(c), "=f"(d) : "r"(addr));
}
__device__ __forceinline__ void sts128(uint32_t addr, const uint32_t* v) {
    asm volatile("st.shared.v4.b32 [%0], {%1,%2,%3,%4};"
                 :: "r"(addr), "r"(v[0]), "r"(v[1]), "r"(v[2]), "r"(v[3]));
}
__device__ __forceinline__ void sts128f(uint32_t addr, float a, float b,
                                        float c, float d) {
    asm volatile("st.shared.v4.f32 [%0], {%1,%2,%3,%4};"
                 :: "r"(addr), "f"(a), "f"(b), "f"(c), "f"(d));
}
// fp16 m16n8k16 mma, fp32 accumulate
__device__ __forceinline__ void mma16(float* d, const uint32_t* A,
                                      uint32_t b0, uint32_t b1) {
    asm volatile(
        "mma.sync.aligned.m16n8k16.row.col.f32.f16.f16.f32 "
        "{%0,%1,%2,%3}, {%4,%5,%6,%7}, {%8,%9}, {%0,%1,%2,%3};"
        : "+f"(d[0]), "+f"(d[1]), "+f"(d[2]), "+f"(d[3])
        : "r"(A[0]), "r"(A[1]), "r"(A[2]), "r"(A[3]), "r"(b0), "r"(b1));
}

// ------------------------- prep -------------------------
__global__ void prep_X(const float* __restrict__ input_r,
                       const float* __restrict__ C_r) {
    int idx = blockIdx.x * blockDim.x + threadIdx.x;   // (c*256+a)*256 + b
    if (idx >= NCOIL * NN * NN) return;
    int c = idx >> 16;
    int a = (idx >> 8) & 255;
    int b = idx & 255;
    float xr = input_r[(a * NN + b) * 2 + 0];
    float xi = input_r[(a * NN + b) * 2 + 1];
    float cr = C_r[(size_t)idx * 2 + 0];
    float ci = C_r[(size_t)idx * 2 + 1];
    float Xr = cr * xr - ci * xi;
    float Xi = cr * xi + ci * xr;

    int ach = a >> 5, col = a & 31;
    int bq = b >> 5, bl = b & 31;
    int blk = bl >> 4, kk = bl & 15;
    int hi = kk >> 3, q = (kk & 7) >> 1, part = kk & 1;

    size_t base = ((size_t)c * 64 + ach * 8 + bq) * SLABH;
    int chA = col * 8 + blk * 4 + q;
    gXh[base + chA * 8 + 0 + hi * 2 + part] = __float2half_rn(Xr);
    gXh[base + chA * 8 + 4 + hi * 2 + part] = __float2half_rn(Xi);
}

// ------------------------- main -------------------------
extern __shared__ char dyn_smem[];

__global__ void __launch_bounds__(THREADS, 1)
main_kernel(const float* __restrict__ angle, const float* __restrict__ w,
            float* __restrict__ out) {
    __shared__ float2 sred[2][KT_CTA];

    const uint32_t XST = smem_u32(dyn_smem);
    const uint32_t TBL = XST + RINGB;
    const uint32_t EPI = TBL + TBLB;
    const int tid  = threadIdx.x;
    const int lane = tid & 31;
    const int warp = tid >> 5;
    const int kw   = warp & 7;        // k-subtile (16 rows, 8 of them = 128 k)
    const int nw   = warp >> 3;       // a-half (16 cols)
    const int r    = lane >> 2;
    const int q    = lane & 3;
    const int kblk = blockIdx.x * KT_CTA;

    const int k0g = kblk + kw * 16 + r;
    const int k1g = k0g + 8;
    const float t0 = angle[2 * k0g + 1];
    const float t1 = angle[2 * k1g + 1];

    // E1 epilogue constants -> private smem slots (frees hot-loop registers)
    const float s_[2] = {angle[2 * k0g], angle[2 * k1g]};
    {
        const int co0 = nw * 16 + 2 * q;
        float fr[2], fi[2], or_[2], oi[2], ar[2], ai[2];
#pragma unroll
        for (int m = 0; m < 2; ++m) {
            sincosf(s_[m] * (float)co0, &oi[m], &or_[m]);
            sincosf(s_[m], &fi[m], &fr[m]);
            sincosf(32.0f * s_[m], &ai[m], &ar[m]);
        }
        uint32_t ea = EPI + (uint32_t)tid * 48;
        sts128f(ea,      or_[0], oi[0], fr[0], fi[0]);
        sts128f(ea + 16, ar[0],  ai[0], or_[1], oi[1]);
        sts128f(ea + 32, fr[1],  fi[1], ar[1],  ai[1]);
    }

    // loader: one STAGE = 512 16B-chunks, 1 per thread; parity swizzle
    auto issue_stage = [&](int st) {
        int cp_ = st >> 6, ach = (st >> 3) & 7, bq = st & 7;
        const char* src =
            (const char*)(gXh + (size_t)((cp_ * 16 + ach) * 8 + bq) * SLABH);
        uint32_t dst = XST + (uint32_t)(st & 7) * STAGEB;
        int ci  = tid >> 8;
        int loc = tid & 255;
        int col = loc >> 3, blk = (loc >> 2) & 1, qq = loc & 3;
        uint32_t doff = (uint32_t)(ci * COILB + col * 128 +
                        ((blk * 64 + qq * 16) ^ ((col & 1) * 64)));
        cp16(dst + doff, src + (size_t)ci * (64 * SLABH * 2) + loc * 16);
    };

    // prologue: window 0 (4 stages) in flight
    issue_stage(0); issue_stage(1); issue_stage(2); issue_stage(3);
    CP_COMMIT();

    // ---- generate E2 fragment table (once per CTA; nw==0 warps, 8 kw) ----
    if (nw == 0) {
        float er_[2][2], ei_[2][2];
        sincosf(t0 * (float)(2 * q - 128), &ei_[0][0], &er_[0][0]);
        sincosf(t0 * (float)(2 * q - 120), &ei_[0][1], &er_[0][1]);
        sincosf(t1 * (float)(2 * q - 128), &ei_[1][0], &er_[1][0]);
        sincosf(t1 * (float)(2 * q - 120), &ei_[1][1], &er_[1][1]);
        float r1r[2], r1i[2], st16r[2], st16i[2];
        sincosf(t0, &r1i[0], &r1r[0]);
        sincosf(t1, &r1i[1], &r1r[1]);
        sincosf(16.0f * t0, &st16i[0], &st16r[0]);
        sincosf(16.0f * t1, &st16i[1], &st16r[1]);

        uint32_t ga = TBL + (uint32_t)kw * 16384 + (uint32_t)lane * 16;
#pragma unroll 4
        for (int bb2 = 0; bb2 < 16; ++bb2) {
            uint32_t Ar[4], Ai[4];
#pragma unroll
            for (int o = 0; o < 2; ++o)
#pragma unroll
                for (int m = 0; m < 2; ++m) {
                    float br = er_[m][o], bi = ei_[m][o];
                    float nr2 = br * r1r[m] - bi * r1i[m];
                    float ni2 = br * r1i[m] + bi * r1r[m];
                    int idx = o * 2 + m;
                    Ar[idx] = pack2(br, nr2);
                    Ai[idx] = pack2(bi, ni2);
                }
            sts128(ga, Ar);
            sts128(ga + 512, Ai);
            ga += 1024;
#pragma unroll
            for (int m = 0; m < 2; ++m)
#pragma unroll
                for (int o = 0; o < 2; ++o) {
                    float nr2 = er_[m][o] * st16r[m] - ei_[m][o] * st16i[m];
                    ei_[m][o] = fmaf(er_[m][o], st16i[m], ei_[m][o] * st16r[m]);
                    er_[m][o] = nr2;
                }
        }
    }

    float yr[2][2] = {}, yi[2][2] = {};
    float runr[2], runi[2];
#pragma unroll
    for (int m = 0; m < 2; ++m) sincosf(-128.0f * s_[m], &runi[m], &runr[m]);

    const uint32_t TA0 = TBL + (uint32_t)kw * 16384 + (uint32_t)lane * 16;
    const uint32_t swz  = (uint32_t)((r & 1) * 64);
    const uint32_t ob0  = (uint32_t)(q * 16) + swz;
    const uint32_t ob1  = (uint32_t)(q * 16) + (64u ^ swz);
    int st = 0;

#pragma unroll 1
    for (int cp = 0; cp < 4; ++cp) {
#pragma unroll 1
        for (int ach = 0; ach < 8; ++ach) {
            float P1[2][2][4] = {}, P2[2][2][4] = {}, P3[2][2][4] = {};

#pragma unroll 1
            for (int grp = 0; grp < 2; ++grp) {       // windows of 4 bq stages
                CP_WAIT0();
                __syncthreads();
                if (st + 4 < NSTAGE) {
                    issue_stage(st + 4); issue_stage(st + 5);
                    issue_stage(st + 6); issue_stage(st + 7);
                    CP_COMMIT();
                }
#pragma unroll
                for (int h = 0; h < 4; ++h) {
                    const int s = st + h;
                    const uint32_t bb  = XST + (uint32_t)(s & 7) * STAGEB;
                    const uint32_t riB = bb + (uint32_t)(nw * 16 + r) * 128;
                    const uint32_t TA  = TA0 + (uint32_t)(s & 7) * 2048;
#pragma unroll
                    for (int blk = 0; blk < 2; ++blk) {
                        const uint32_t ob = blk ? ob1 : ob0;
                        // batch 4 independent B loads (MLP) before compute
                        uint32_t B[2][2][4];
#pragma unroll
                        for (int ci = 0; ci < 2; ++ci)
#pragma unroll
                            for (int nt = 0; nt < 2; ++nt)
                                lds128(B[ci][nt][0], B[ci][nt][1],
                                       B[ci][nt][2], B[ci][nt][3],
                                       riB + ci * COILB + nt * 1024 + ob);
                        uint32_t Ar[4], Ai[4], As[4];
                        lds128(Ar[0], Ar[1], Ar[2], Ar[3], TA + blk * 1024);
                        lds128(Ai[0], Ai[1], Ai[2], Ai[3], TA + blk * 1024 + 512);
#pragma unroll
                        for (int j = 0; j < 4; ++j) As[j] = hadd2u(Ar[j], Ai[j]);
#pragma unroll
                        for (int ci = 0; ci < 2; ++ci)
#pragma unroll
                            for (int nt = 0; nt < 2; ++nt) {
                                uint32_t rlo = B[ci][nt][0], rhi = B[ci][nt][1];
                                uint32_t ilo = B[ci][nt][2], ihi = B[ci][nt][3];
                                uint32_t slo = hadd2u(rlo, ilo);
                                uint32_t shi = hadd2u(rhi, ihi);
                                mma16(P1[ci][nt], Ar, rlo, rhi);
                                mma16(P2[ci][nt], Ai, ilo, ihi);
                                mma16(P3[ci][nt], As, slo, shi);
                            }
                    }
                }
                st += 4;
            }

            // ---- epilogue: y += e1 * T (3M combine); consts from smem ----
            float fc0r[2], fc0i[2], f1r[2], f1i[2], advr[2], advi[2];
            {
                uint32_t ea = EPI + (uint32_t)tid * 48;
                lds128f(fc0r[0], fc0i[0], f1r[0], f1i[0], ea);
                lds128f(advr[0], advi[0], fc0r[1], fc0i[1], ea + 16);
                lds128f(f1r[1], f1i[1], advr[1], advi[1], ea + 32);
            }
#pragma unroll
            for (int m = 0; m < 2; ++m) {
                // f8 = f1^8 by repeated squaring
                float c2 = f1r[m] * f1r[m] - f1i[m] * f1i[m];
                float sq2 = 2.0f * f1r[m] * f1i[m];
                float c4 = c2 * c2 - sq2 * sq2;
                float sq4 = 2.0f * c2 * sq2;
                float f8r = c4 * c4 - sq4 * sq4;
                float f8i = 2.0f * c4 * sq4;

                float b0r = runr[m] * fc0r[m] - runi[m] * fc0i[m];
                float b0i = runr[m] * fc0i[m] + runi[m] * fc0r[m];
#pragma unroll
                for (int nt = 0; nt < 2; ++nt) {
                    float cr_ = b0r, ci_ = b0i;
                    if (nt == 1) {
                        cr_ = b0r * f8r - b0i * f8i;
                        ci_ = b0r * f8i + b0i * f8r;
                    }
#pragma unroll
                    for (int j = 0; j < 2; ++j) {
                        float er2 = cr_, ei2 = ci_;
                        if (j == 1) {
                            er2 = cr_ * f1r[m] - ci_ * f1i[m];
                            ei2 = cr_ * f1i[m] + ci_ * f1r[m];
                        }
                        int e = m * 2 + j;
#pragma unroll
                        for (int ci2 = 0; ci2 < 2; ++ci2) {
                            float p1 = P1[ci2][nt][e], p2 = P2[ci2][nt][e];
                            float Tr = p1 - p2;
                            float Ti = P3[ci2][nt][e] - p1 - p2;
                            yr[ci2][m] = fmaf(er2, Tr, yr[ci2][m]);
                            yr[ci2][m] = fmaf(-ei2, Ti, yr[ci2][m]);
                            yi[ci2][m] = fmaf(er2, Ti, yi[ci2][m]);
                            yi[ci2][m] = fmaf(ei2, Tr, yi[ci2][m]);
                        }
                    }
                }
                // advance run by exp(i*32*s)
                float nr2 = runr[m] * advr[m] - runi[m] * advi[m];
                runi[m] = fmaf(runr[m], advi[m], runi[m] * advr[m]);
                runr[m] = nr2;
            }
        } // ach

        // ---- writeout coil pair cp ----
#pragma unroll
        for (int ci = 0; ci < 2; ++ci)
#pragma unroll
            for (int m = 0; m < 2; ++m) {
                yr[ci][m] += __shfl_xor_sync(0xffffffffu, yr[ci][m], 1);
                yr[ci][m] += __shfl_xor_sync(0xffffffffu, yr[ci][m], 2);
                yi[ci][m] += __shfl_xor_sync(0xffffffffu, yi[ci][m], 1);
                yi[ci][m] += __shfl_xor_sync(0xffffffffu, yi[ci][m], 2);
            }
        if (nw == 1 && q == 0) {
            sred[0][kw * 16 + r]     = make_float2(yr[0][0], yi[0][0]);
            sred[0][kw * 16 + 8 + r] = make_float2(yr[0][1], yi[0][1]);
            sred[1][kw * 16 + r]     = make_float2(yr[1][0], yi[1][0]);
            sred[1][kw * 16 + 8 + r] = make_float2(yr[1][1], yi[1][1]);
        }
        __syncthreads();
        if (nw == 0 && q == 0) {
            const float wk0 = w[k0g & (NVEC - 1)];
            const float wk1 = w[k1g & (NVEC - 1)];
            int c0 = cp * 2;
#pragma unroll
            for (int ci = 0; ci < 2; ++ci) {
                float2 p0 = sred[ci][kw * 16 + r];
                float2 p1 = sred[ci][kw * 16 + 8 + r];
                size_t o0 = ((size_t)(c0 + ci) * KTOT + k0g) * 2;
                size_t o1 = ((size_t)(c0 + ci) * KTOT + k1g) * 2;
                out[o0 + 0] = (yr[ci][0] + p0.x) * wk0;
                out[o0 + 1] = (yi[ci][0] + p0.y) * wk0;
                out[o1 + 0] = (yr[ci][1] + p1.x) * wk1;
                out[o1 + 1] = (yi[ci][1] + p1.y) * wk1;
            }
        }
        __syncthreads();   // sred reuse safety
#pragma unroll
        for (int ci = 0; ci < 2; ++ci)
#pragma unroll
            for (int m = 0; m < 2; ++m) { yr[ci][m] = 0.f; yi[ci][m] = 0.f; }
#pragma unroll
        for (int m = 0; m < 2; ++m)
            sincosf(-128.0f * s_[m], &runi[m], &runr[m]);
    } // cp
}

// ------------------------- launch -------------------------
extern "C" void kernel_launch(void* const* d_in, const int* in_sizes, int n_in,
                              void* d_out, int out_size) {
    const float* input_r = (const float*)d_in[0];
    const float* C_r     = (const float*)d_in[1];
    const float* w       = (const float*)d_in[2];
    const float* angle   = (const float*)d_in[3];
    float* out = (float*)d_out;

    prep_X<<<(NCOIL * NN * NN + 255) / 256, 256>>>(input_r, C_r);

    cudaFuncSetAttribute(main_kernel,
                         cudaFuncAttributeMaxDynamicSharedMemorySize, SMEM_BYTES);
    main_kernel<<<NCTA, THREADS, SMEM_BYTES>>>(angle, w, out);
}